// round 1
// baseline (speedup 1.0000x reference)
#include <cuda_runtime.h>
#include <math.h>

#define BATCH   16
#define NPTS    256
#define FDIM    64
#define FPRIME  16
#define HDIM    128
#define TLUT    256
#define DMAX    1.7321f
#define ITILE   16
#define MAIN_THREADS 512

// Scratch (no cudaMalloc allowed): raw LUT values g(d_t) and packed (value,slope) LUT.
__device__ float  g_lut_raw[(TLUT + 1) * FDIM];
__device__ float4 g_lut4[TLUT * (FDIM / 2)];

__device__ __forceinline__ float sp(float x) {
    // numerically stable softplus, matches jax.nn.softplus
    return fmaxf(x, 0.0f) + log1pf(expf(-fabsf(x)));
}

// ---------------------------------------------------------------------------
// Kernel 1: tabulate g(d) = softplus(softplus(d*w1+b1) @ w2 + b2) at T+1 knots
// ---------------------------------------------------------------------------
__global__ void build_lut_kernel(const float* __restrict__ mp_w1,
                                 const float* __restrict__ mp_b1,
                                 const float* __restrict__ mp_w2,
                                 const float* __restrict__ mp_b2) {
    __shared__ float hid[HDIM];
    const int t = blockIdx.x;                       // 0..TLUT
    const float d = (float)t * (DMAX / (float)TLUT);
    const int h = threadIdx.x;                      // 128 threads
    hid[h] = sp(fmaf(d, mp_w1[h], mp_b1[h]));
    __syncthreads();
    if (h < FDIM) {
        float a = mp_b2[h];
        #pragma unroll 8
        for (int k = 0; k < HDIM; k++)
            a = fmaf(hid[k], mp_w2[k * FDIM + h], a);
        g_lut_raw[t * FDIM + h] = sp(a);
    }
}

// ---------------------------------------------------------------------------
// Kernel 2: pack LUT rows as (v0, dv0, v1, dv1) per f-pair for single LDS.128
// ---------------------------------------------------------------------------
__global__ void pack_lut_kernel() {
    int idx = blockIdx.x * blockDim.x + threadIdx.x;
    if (idx >= TLUT * (FDIM / 2)) return;
    int t = idx >> 5, p = idx & 31;
    float v0 = g_lut_raw[t * FDIM + 2 * p];
    float v1 = g_lut_raw[t * FDIM + 2 * p + 1];
    float u0 = g_lut_raw[(t + 1) * FDIM + 2 * p];
    float u1 = g_lut_raw[(t + 1) * FDIM + 2 * p + 1];
    g_lut4[idx] = make_float4(v0, u0 - v0, v1, u1 - v1);
}

// ---------------------------------------------------------------------------
// Kernel 3: main fused kernel.
//   Stage 1: acc[i,f] = sum_j g(d_ij)[f] * fb[j,f]   (LUT interp, SMEM-resident)
//   Stage 2: f_bar = sp(acc); h2 = sp(f_bar@pc_w1+b1); out = sp(h2@pc_w2+b2)
// SMEM: [0,128K) LUT | [128K,192K) f tile | [192K,196K) r tile
// Stage-2 overlays (after syncs): fbar@0, h2@4K, pc_w1@128K, pc_w2@160K, biases
// ---------------------------------------------------------------------------
__global__ __launch_bounds__(MAIN_THREADS, 1)
void property_predictor_main(const float* __restrict__ r,
                             const float* __restrict__ f,
                             const float* __restrict__ pc_w1,
                             const float* __restrict__ pc_b1,
                             const float* __restrict__ pc_w2,
                             const float* __restrict__ pc_b2,
                             float* __restrict__ out) {
    extern __shared__ char smem[];
    float4* lutS  = (float4*)(smem);                 // 256*32*16 = 131072 B
    float2* fbS   = (float2*)(smem + 131072);        // 256*32*8  =  65536 B
    float4* rS    = (float4*)(smem + 196608);        // 256*16    =   4096 B
    // stage-2 overlays
    float*  fbarS = (float*)(smem);                  // 16*64*4 = 4096 B (over LUT)
    float*  h2S   = (float*)(smem + 4096);           // 16*128*4 = 8192 B (over LUT)
    float*  w1S   = (float*)(smem + 131072);         // 64*128*4 = 32768 B (over fb)
    float*  w2S   = (float*)(smem + 163840);         // 128*16*4 = 8192 B (over fb)
    float*  b1S   = (float*)(smem + 172032);         // 512 B
    float*  b2S   = (float*)(smem + 172544);         // 64 B

    const int b    = blockIdx.y;
    const int i0   = blockIdx.x * ITILE;
    const int tid  = threadIdx.x;
    const int w    = tid >> 5;
    const int lane = tid & 31;

    // cooperative tile loads
    for (int k = tid; k < TLUT * 32; k += MAIN_THREADS) lutS[k] = g_lut4[k];
    const float2* fbG = (const float2*)(f + (size_t)b * NPTS * FDIM);
    for (int k = tid; k < NPTS * 32; k += MAIN_THREADS) fbS[k] = fbG[k];
    const float* rG = r + (size_t)b * NPTS * 3;
    for (int k = tid; k < NPTS; k += MAIN_THREADS)
        rS[k] = make_float4(rG[3 * k], rG[3 * k + 1], rG[3 * k + 2], 0.0f);
    __syncthreads();

    // ---- Stage 1: warp w owns row i; lane owns features (2*lane, 2*lane+1) ----
    const int i = i0 + w;
    const float4 ri = rS[i];
    const float scale = (float)TLUT / DMAX;
    float acc0 = 0.0f, acc1 = 0.0f;

    #pragma unroll 4
    for (int j = 0; j < NPTS; j++) {
        float4 rj = rS[j];                           // warp-broadcast
        float dx = ri.x - rj.x, dy = ri.y - rj.y, dz = ri.z - rj.z;
        float d  = sqrtf(fmaf(dx, dx, fmaf(dy, dy, dz * dz)));
        float t  = fminf(d * scale, (float)TLUT - 0.001f);
        int   it = (int)t;                           // warp-uniform
        float fr = t - (float)it;
        float4 L  = lutS[(it << 5) + lane];          // (v0,dv0,v1,dv1) conflict-free
        float2 fv = fbS[(j << 5) + lane];
        acc0 = fmaf(fmaf(fr, L.y, L.x), fv.x, acc0);
        acc1 = fmaf(fmaf(fr, L.w, L.z), fv.y, acc1);
    }
    __syncthreads();   // everyone done reading lutS/fbS before overlay writes

    // f_bar into overlay; load pointwise-MLP weights into fb overlay
    fbarS[w * FDIM + 2 * lane]     = sp(acc0);
    fbarS[w * FDIM + 2 * lane + 1] = sp(acc1);
    for (int k = tid; k < FDIM * HDIM;   k += MAIN_THREADS) w1S[k] = pc_w1[k];
    for (int k = tid; k < HDIM * FPRIME; k += MAIN_THREADS) w2S[k] = pc_w2[k];
    if (tid < HDIM)   b1S[tid] = pc_b1[tid];
    if (tid < FPRIME) b2S[tid] = pc_b2[tid];
    __syncthreads();

    // ---- Stage 2: warp w computes row i. h2: lane owns h = lane + 32k ----
    float h0 = b1S[lane], h1 = b1S[lane + 32], h2v = b1S[lane + 64], h3 = b1S[lane + 96];
    #pragma unroll 4
    for (int ff = 0; ff < FDIM; ff++) {
        float fv = fbarS[w * FDIM + ff];             // warp-broadcast
        h0  = fmaf(fv, w1S[ff * HDIM + lane],      h0);
        h1  = fmaf(fv, w1S[ff * HDIM + lane + 32], h1);
        h2v = fmaf(fv, w1S[ff * HDIM + lane + 64], h2v);
        h3  = fmaf(fv, w1S[ff * HDIM + lane + 96], h3);
    }
    h2S[w * HDIM + lane]      = sp(h0);
    h2S[w * HDIM + lane + 32] = sp(h1);
    h2S[w * HDIM + lane + 64] = sp(h2v);
    h2S[w * HDIM + lane + 96] = sp(h3);
    __syncwarp();

    if (lane < FPRIME) {
        float o = b2S[lane];
        #pragma unroll 8
        for (int hh = 0; hh < HDIM; hh++)
            o = fmaf(h2S[w * HDIM + hh], w2S[hh * FPRIME + lane], o);
        out[((size_t)(b * NPTS + i)) * FPRIME + lane] = sp(o);
    }
}

// ---------------------------------------------------------------------------
extern "C" void kernel_launch(void* const* d_in, const int* in_sizes, int n_in,
                              void* d_out, int out_size) {
    const float* r     = (const float*)d_in[0];
    const float* f     = (const float*)d_in[1];
    const float* mp_w1 = (const float*)d_in[2];
    const float* mp_b1 = (const float*)d_in[3];
    const float* mp_w2 = (const float*)d_in[4];
    const float* mp_b2 = (const float*)d_in[5];
    const float* pc_w1 = (const float*)d_in[6];
    const float* pc_b1 = (const float*)d_in[7];
    const float* pc_w2 = (const float*)d_in[8];
    const float* pc_b2 = (const float*)d_in[9];
    float* out = (float*)d_out;

    build_lut_kernel<<<TLUT + 1, HDIM>>>(mp_w1, mp_b1, mp_w2, mp_b2);
    pack_lut_kernel<<<(TLUT * 32 + 255) / 256, 256>>>();

    cudaFuncSetAttribute(property_predictor_main,
                         cudaFuncAttributeMaxDynamicSharedMemorySize, 200704);
    dim3 grid(NPTS / ITILE, BATCH);
    property_predictor_main<<<grid, MAIN_THREADS, 200704>>>(
        r, f, pc_w1, pc_b1, pc_w2, pc_b2, out);
}

// round 2
// speedup vs baseline: 2.5048x; 2.5048x over previous
#include <cuda_runtime.h>
#include <cuda_fp16.h>
#include <math.h>

#define BATCH   16
#define NPTS    256
#define FDIM    64
#define FPRIME  16
#define HDIM    128
#define TLUT    128
#define DMAX    1.7321f
#define ITILE   32
#define MAIN_THREADS 1024

// packed fp16 LUT: entry [t*32+p] = { half2(v_{2p}, v_{2p+1}), half2(dv_{2p}, dv_{2p+1}) }
__device__ uint2 g_lutH[TLUT * 32];

__device__ __forceinline__ float sp(float x) {
    return fmaxf(x, 0.0f) + log1pf(expf(-fabsf(x)));
}

// ---------------------------------------------------------------------------
// LUT build: block t computes knots t and t+1, writes packed fp16 row t.
// mp_w2 staged in smem -> no DRAM-latency-bound dot loop.
// ---------------------------------------------------------------------------
__global__ __launch_bounds__(128)
void build_lut_kernel(const float* __restrict__ mp_w1,
                      const float* __restrict__ mp_b1,
                      const float* __restrict__ mp_w2,
                      const float* __restrict__ mp_b2) {
    __shared__ float w2s[HDIM * FDIM];     // 32 KB
    __shared__ float hidA[HDIM], hidB[HDIM];
    __shared__ float vA[FDIM], vB[FDIM];

    const int t   = blockIdx.x;            // 0..TLUT-1
    const int tid = threadIdx.x;           // 128
    const float step = DMAX / (float)TLUT;
    const float dA = (float)t * step;
    const float dB = (float)(t + 1) * step;

    #pragma unroll 16
    for (int k = tid; k < HDIM * FDIM; k += 128) w2s[k] = mp_w2[k];
    {
        float w1 = mp_w1[tid], b1 = mp_b1[tid];
        hidA[tid] = sp(fmaf(dA, w1, b1));
        hidB[tid] = sp(fmaf(dB, w1, b1));
    }
    __syncthreads();

    if (tid < FDIM) {
        float a = mp_b2[tid], b = a;
        #pragma unroll 8
        for (int k = 0; k < HDIM; k++) {
            float w = w2s[k * FDIM + tid];
            a = fmaf(hidA[k], w, a);
            b = fmaf(hidB[k], w, b);
        }
        vA[tid] = sp(a);
        vB[tid] = sp(b);
    }
    __syncthreads();

    if (tid < 32) {
        float a0 = vA[2 * tid], a1 = vA[2 * tid + 1];
        float b0 = vB[2 * tid], b1 = vB[2 * tid + 1];
        __half2 vh  = __floats2half2_rn(a0, a1);
        __half2 dvh = __floats2half2_rn(b0 - a0, b1 - a1);
        uint2 e;
        e.x = *reinterpret_cast<unsigned int*>(&vh);
        e.y = *reinterpret_cast<unsigned int*>(&dvh);
        g_lutH[t * 32 + tid] = e;
    }
}

// ---------------------------------------------------------------------------
// Main fused kernel. CTA = (batch b, 32-row i-tile). 1024 threads, 1 CTA/SM.
// SMEM map (stage 1):
//   [0,      32768)  lutH   fp16 packed LUT            (TLUT*32 uint2)
//   [32768,  65536)  fbH    f tile as half2             (256*32)
//   [65536,  69632)  rS     positions as float4         (256)
//   [69632, 135168)  tS     per-pair {byteoff, fr_h2}   (32*256 uint2)
// Stage-2 overlays (post-sync): fbar@0, h2(stride132)@8192, w1@25600,
//   w2@58368, b1@66560, b2@67072
// ---------------------------------------------------------------------------
__global__ __launch_bounds__(MAIN_THREADS, 1)
void property_predictor_main(const float* __restrict__ r,
                             const float* __restrict__ f,
                             const float* __restrict__ pc_w1,
                             const float* __restrict__ pc_b1,
                             const float* __restrict__ pc_w2,
                             const float* __restrict__ pc_b2,
                             float* __restrict__ out) {
    extern __shared__ char smem[];
    uint2*        lutS = (uint2*)(smem);
    unsigned int* fbS  = (unsigned int*)(smem + 32768);
    float4*       rS   = (float4*)(smem + 65536);
    uint2*        tS   = (uint2*)(smem + 69632);
    // stage-2 overlays
    float* fbarS = (float*)(smem);             // 32*64
    float* h2S   = (float*)(smem + 8192);      // 32*132 (padded stride)
    float* w1S   = (float*)(smem + 25600);     // 64*128
    float* w2S   = (float*)(smem + 58368);     // 128*16
    float* b1S   = (float*)(smem + 66560);     // 128
    float* b2S   = (float*)(smem + 67072);     // 16

    const int b    = blockIdx.y;
    const int i0   = blockIdx.x * ITILE;
    const int tid  = threadIdx.x;
    const int w    = tid >> 5;
    const int lane = tid & 31;

    // ---- tile loads ----
    #pragma unroll 4
    for (int k = tid; k < TLUT * 32; k += MAIN_THREADS) lutS[k] = g_lutH[k];
    const float2* fbG = (const float2*)(f + (size_t)b * NPTS * FDIM);
    #pragma unroll 8
    for (int k = tid; k < NPTS * 32; k += MAIN_THREADS) {
        float2 v = fbG[k];
        __half2 h = __floats2half2_rn(v.x, v.y);
        fbS[k] = *reinterpret_cast<unsigned int*>(&h);
    }
    const float* rG = r + (size_t)b * NPTS * 3;
    if (tid < NPTS)
        rS[tid] = make_float4(rG[3 * tid], rG[3 * tid + 1], rG[3 * tid + 2], 0.0f);
    __syncthreads();

    // ---- stage A: precompute (lut byte-offset, fr as half2) per (i,j) pair ----
    const float scale = (float)TLUT / DMAX;
    #pragma unroll
    for (int k = 0; k < (ITILE * NPTS) / MAIN_THREADS; k++) {
        int idx = tid + k * MAIN_THREADS;
        int ww = idx >> 8, jj = idx & 255;
        float4 ri = rS[i0 - i0 + ww + (i0 & 0)];  // placeholder avoided below
        ri = rS[i0 + ww];
        float4 rj = rS[jj];
        float dx = ri.x - rj.x, dy = ri.y - rj.y, dz = ri.z - rj.z;
        float d  = sqrtf(fmaf(dx, dx, fmaf(dy, dy, dz * dz)));
        float t  = fminf(d * scale, (float)TLUT - 0.001f);
        int   it = (int)t;
        float fr = t - (float)it;
        __half2 fr2 = __float2half2_rn(fr);
        uint2 e;
        e.x = (unsigned int)(it << 8);            // byte offset: it * 32 entries * 8B
        e.y = *reinterpret_cast<unsigned int*>(&fr2);
        tS[idx] = e;
    }
    __syncthreads();

    // ---- stage 1: warp w owns row i0+w... wait, w in [0,32), row i = i0+w ----
    const char*  lutLane = smem + (size_t)lane * 8;
    const uint2* tRow    = tS + w * NPTS;
    float acc0 = 0.0f, acc1 = 0.0f;
    #pragma unroll 8
    for (int j = 0; j < NPTS; j++) {
        uint2 e = tRow[j];                                   // warp-broadcast
        uint2 L = *(const uint2*)(lutLane + e.x);            // 2-phase LDS
        __half2 fr2 = *reinterpret_cast<__half2*>(&e.y);
        __half2 v2  = *reinterpret_cast<__half2*>(&L.x);
        __half2 dv2 = *reinterpret_cast<__half2*>(&L.y);
        __half2 g2  = __hfma2(fr2, dv2, v2);
        unsigned int fbits = fbS[(j << 5) + lane];
        __half2 fb2 = *reinterpret_cast<__half2*>(&fbits);
        __half2 q2  = __hmul2(g2, fb2);
        float2 qf = __half22float2(q2);
        acc0 += qf.x;
        acc1 += qf.y;
    }
    float fb0 = sp(acc0), fb1 = sp(acc1);
    __syncthreads();   // all reads of lutS/fbS/tS done before overlays

    // ---- write f_bar; stage pointwise-MLP weights ----
    fbarS[w * FDIM + 2 * lane]     = fb0;
    fbarS[w * FDIM + 2 * lane + 1] = fb1;
    #pragma unroll 8
    for (int k = tid; k < FDIM * HDIM;   k += MAIN_THREADS) w1S[k] = pc_w1[k];
    #pragma unroll 2
    for (int k = tid; k < HDIM * FPRIME; k += MAIN_THREADS) w2S[k] = pc_w2[k];
    if (tid < HDIM)   b1S[tid] = pc_b1[tid];
    if (tid < FPRIME) b2S[tid] = pc_b2[tid];
    __syncthreads();

    // ---- stage 2, layer 1: warps 0..7, 4 rows each; lane owns 4 h-cols ----
    if (w < 8) {
        float acc[4][4];
        #pragma unroll
        for (int kk = 0; kk < 4; kk++) {
            float bv = b1S[lane + 32 * kk];
            #pragma unroll
            for (int rr = 0; rr < 4; rr++) acc[rr][kk] = bv;
        }
        #pragma unroll 4
        for (int ff = 0; ff < FDIM; ff++) {
            float w1v[4];
            #pragma unroll
            for (int kk = 0; kk < 4; kk++) w1v[kk] = w1S[ff * HDIM + lane + 32 * kk];
            #pragma unroll
            for (int rr = 0; rr < 4; rr++) {
                float fv = fbarS[(4 * w + rr) * FDIM + ff];  // broadcast
                #pragma unroll
                for (int kk = 0; kk < 4; kk++) acc[rr][kk] = fmaf(fv, w1v[kk], acc[rr][kk]);
            }
        }
        #pragma unroll
        for (int rr = 0; rr < 4; rr++)
            #pragma unroll
            for (int kk = 0; kk < 4; kk++)
                h2S[(4 * w + rr) * 132 + lane + 32 * kk] = sp(acc[rr][kk]);
    }
    __syncthreads();

    // ---- stage 2, layer 2: 512 threads = (row i, out-col p) ----
    if (tid < ITILE * FPRIME) {
        int i = tid >> 4, p = tid & 15;
        float o = b2S[p];
        #pragma unroll 8
        for (int hh = 0; hh < HDIM; hh++)
            o = fmaf(h2S[i * 132 + hh], w2S[hh * FPRIME + p], o);
        out[((size_t)(b * NPTS + i0 + i)) * FPRIME + p] = sp(o);
    }
}

// ---------------------------------------------------------------------------
extern "C" void kernel_launch(void* const* d_in, const int* in_sizes, int n_in,
                              void* d_out, int out_size) {
    const float* r     = (const float*)d_in[0];
    const float* f     = (const float*)d_in[1];
    const float* mp_w1 = (const float*)d_in[2];
    const float* mp_b1 = (const float*)d_in[3];
    const float* mp_w2 = (const float*)d_in[4];
    const float* mp_b2 = (const float*)d_in[5];
    const float* pc_w1 = (const float*)d_in[6];
    const float* pc_b1 = (const float*)d_in[7];
    const float* pc_w2 = (const float*)d_in[8];
    const float* pc_b2 = (const float*)d_in[9];
    float* out = (float*)d_out;

    build_lut_kernel<<<TLUT, 128>>>(mp_w1, mp_b1, mp_w2, mp_b2);

    static int configured = 0;
    if (!configured) {
        cudaFuncSetAttribute(property_predictor_main,
                             cudaFuncAttributeMaxDynamicSharedMemorySize, 135168);
        configured = 1;
    }
    dim3 grid(NPTS / ITILE, BATCH);
    property_predictor_main<<<grid, MAIN_THREADS, 135168>>>(
        r, f, pc_w1, pc_b1, pc_w2, pc_b2, out);
}

// round 3
// speedup vs baseline: 3.0172x; 1.2046x over previous
#include <cuda_runtime.h>
#include <cuda_fp16.h>
#include <math.h>

#define BATCH   16
#define NPTS    256
#define FDIM    64
#define FPRIME  16
#define HDIM    128
#define TLUT    512
#define DMAX    1.7321f
#define ITILE   32
#define MAIN_THREADS 1024

// nearest-neighbor LUT: entry [t*32+p] = half2(v_{2p}(t*h), v_{2p+1}(t*h))
__device__ unsigned int g_lutH[TLUT * 32];

__device__ __forceinline__ float sp(float x) {
    return fmaxf(x, 0.0f) + log1pf(expf(-fabsf(x)));
}

// ---------------------------------------------------------------------------
// LUT build: 64 blocks x 8 knots. w2 staged once per block, 8-wide ILP dot.
// ---------------------------------------------------------------------------
__global__ __launch_bounds__(128)
void build_lut_kernel(const float* __restrict__ mp_w1,
                      const float* __restrict__ mp_b1,
                      const float* __restrict__ mp_w2,
                      const float* __restrict__ mp_b2) {
    __shared__ float w2s[HDIM * FDIM];     // 32 KB
    __shared__ float hid[8][HDIM];
    __shared__ float v[8][FDIM];

    const int blk = blockIdx.x;            // 0..63
    const int tid = threadIdx.x;           // 128
    const float h = DMAX / (float)TLUT;

    #pragma unroll 16
    for (int k = tid; k < HDIM * FDIM; k += 128) w2s[k] = mp_w2[k];
    {
        float w1 = mp_w1[tid], b1 = mp_b1[tid];
        #pragma unroll
        for (int e = 0; e < 8; e++) {
            float d = (float)(blk * 8 + e) * h;
            hid[e][tid] = sp(fmaf(d, w1, b1));
        }
    }
    __syncthreads();

    if (tid < FDIM) {
        float a[8];
        float b2 = mp_b2[tid];
        #pragma unroll
        for (int e = 0; e < 8; e++) a[e] = b2;
        #pragma unroll 4
        for (int k = 0; k < HDIM; k++) {
            float w = w2s[k * FDIM + tid];
            #pragma unroll
            for (int e = 0; e < 8; e++) a[e] = fmaf(hid[e][k], w, a[e]);
        }
        #pragma unroll
        for (int e = 0; e < 8; e++) v[e][tid] = sp(a[e]);
    }
    __syncthreads();

    for (int idx = tid; idx < 8 * 32; idx += 128) {
        int e = idx >> 5, p = idx & 31;
        __half2 vh = __floats2half2_rn(v[e][2 * p], v[e][2 * p + 1]);
        g_lutH[(blk * 8 + e) * 32 + p] = *reinterpret_cast<unsigned int*>(&vh);
    }
}

// ---------------------------------------------------------------------------
// Main fused kernel. CTA = (batch b, 32-row i-tile). 1024 threads.
// SMEM map (stage 1), 118784 B total:
//   [0,      65536)  lutS  fp16 LUT (TLUT*32 half2)
//   [65536,  98304)  fbS   f tile as half2 (256*32)
//   [98304, 114688)  tS    per-pair u16 LUT byte-offset (32*256)
//   [114688,118784)  rS    positions as float4 (256)
// Stage-2 overlays (post-sync): fbar@0, h2@8192(stride132), w1@65536,
//   w2@98304, b1@106496, b2@107008
// ---------------------------------------------------------------------------
__global__ __launch_bounds__(MAIN_THREADS, 1)
void property_predictor_main(const float* __restrict__ r,
                             const float* __restrict__ f,
                             const float* __restrict__ pc_w1,
                             const float* __restrict__ pc_b1,
                             const float* __restrict__ pc_w2,
                             const float* __restrict__ pc_b2,
                             float* __restrict__ out) {
    extern __shared__ char smem[];
    unsigned int*   lutS = (unsigned int*)(smem);
    unsigned int*   fbS  = (unsigned int*)(smem + 65536);
    unsigned short* tS   = (unsigned short*)(smem + 98304);
    float4*         rS   = (float4*)(smem + 114688);
    // stage-2 overlays
    float* fbarS = (float*)(smem);             // 32*64
    float* h2S   = (float*)(smem + 8192);      // 32*132 padded
    float* w1S   = (float*)(smem + 65536);     // 64*128
    float* w2S   = (float*)(smem + 98304);     // 128*16
    float* b1S   = (float*)(smem + 106496);    // 128
    float* b2S   = (float*)(smem + 107008);    // 16

    const int b    = blockIdx.y;
    const int i0   = blockIdx.x * ITILE;
    const int tid  = threadIdx.x;
    const int w    = tid >> 5;
    const int lane = tid & 31;

    // ---- tile loads ----
    #pragma unroll 4
    for (int k = tid; k < TLUT * 32; k += MAIN_THREADS) lutS[k] = g_lutH[k];
    const float2* fbG = (const float2*)(f + (size_t)b * NPTS * FDIM);
    #pragma unroll 8
    for (int k = tid; k < NPTS * 32; k += MAIN_THREADS) {
        float2 v = fbG[k];
        __half2 hv = __floats2half2_rn(v.x, v.y);
        fbS[k] = *reinterpret_cast<unsigned int*>(&hv);
    }
    const float* rG = r + (size_t)b * NPTS * 3;
    if (tid < NPTS)
        rS[tid] = make_float4(rG[3 * tid], rG[3 * tid + 1], rG[3 * tid + 2], 0.0f);
    __syncthreads();

    // ---- stage A: per-pair nearest-knot byte offset (u16) ----
    const float scale = (float)TLUT / DMAX;
    #pragma unroll
    for (int k = 0; k < (ITILE * NPTS) / MAIN_THREADS; k++) {
        int idx = tid + k * MAIN_THREADS;
        int ww = idx >> 8, jj = idx & 255;
        float4 ri = rS[i0 + ww];
        float4 rj = rS[jj];
        float dx = ri.x - rj.x, dy = ri.y - rj.y, dz = ri.z - rj.z;
        float d  = sqrtf(fmaf(dx, dx, fmaf(dy, dy, dz * dz)));
        int   it = (int)(fmaf(d, scale, 0.5f));
        it = min(it, TLUT - 1);
        tS[idx] = (unsigned short)(it << 7);       // byte offset: it * 32 * 4
    }
    __syncthreads();

    // ---- stage 1: warp w owns row i0+w; lane owns features (2*lane,2*lane+1)
    const char*  lutLane = smem + (size_t)lane * 4;
    const uint2* tRow4   = (const uint2*)(smem + 98304 + (size_t)w * 512);
    const unsigned int* fbL = fbS + lane;

    float accx = 0.0f, accy = 0.0f;
    const __half2 hzero = __floats2half2_rn(0.0f, 0.0f);
    #pragma unroll 4
    for (int k8 = 0; k8 < NPTS / 8; k8++) {        // 8 j's per iteration
        uint2 q0 = tRow4[2 * k8];                  // offsets j0..j3 (broadcast)
        uint2 q1 = tRow4[2 * k8 + 1];              // offsets j4..j7
        unsigned int off[8];
        off[0] = q0.x & 0xFFFFu;  off[1] = q0.x >> 16;
        off[2] = q0.y & 0xFFFFu;  off[3] = q0.y >> 16;
        off[4] = q1.x & 0xFFFFu;  off[5] = q1.x >> 16;
        off[6] = q1.y & 0xFFFFu;  off[7] = q1.y >> 16;

        __half2 acc8 = hzero;
        #pragma unroll
        for (int jj = 0; jj < 8; jj++) {
            __half2 L  = *(const __half2*)(lutLane + off[jj]);
            unsigned int fbits = fbL[(8 * k8 + jj) << 5];
            __half2 fb2 = *reinterpret_cast<__half2*>(&fbits);
            acc8 = __hfma2(L, fb2, acc8);
        }
        float2 t2 = __half22float2(acc8);          // flush partials to fp32
        accx += t2.x;
        accy += t2.y;
    }
    float fb0 = sp(accx), fb1 = sp(accy);
    __syncthreads();   // all stage-1 reads done before overlay writes

    // ---- write f_bar; stage pointwise-MLP weights into overlays ----
    fbarS[w * FDIM + 2 * lane]     = fb0;
    fbarS[w * FDIM + 2 * lane + 1] = fb1;
    #pragma unroll 8
    for (int k = tid; k < FDIM * HDIM;   k += MAIN_THREADS) w1S[k] = pc_w1[k];
    #pragma unroll 2
    for (int k = tid; k < HDIM * FPRIME; k += MAIN_THREADS) w2S[k] = pc_w2[k];
    if (tid < HDIM)   b1S[tid] = pc_b1[tid];
    if (tid < FPRIME) b2S[tid] = pc_b2[tid];
    __syncthreads();

    // ---- stage 2, layer 1: warps 0..7, 4 rows each; lane owns 4 h-cols ----
    if (w < 8) {
        float acc[4][4];
        #pragma unroll
        for (int kk = 0; kk < 4; kk++) {
            float bv = b1S[lane + 32 * kk];
            #pragma unroll
            for (int rr = 0; rr < 4; rr++) acc[rr][kk] = bv;
        }
        #pragma unroll 4
        for (int ff = 0; ff < FDIM; ff++) {
            float w1v[4];
            #pragma unroll
            for (int kk = 0; kk < 4; kk++) w1v[kk] = w1S[ff * HDIM + lane + 32 * kk];
            #pragma unroll
            for (int rr = 0; rr < 4; rr++) {
                float fv = fbarS[(4 * w + rr) * FDIM + ff];
                #pragma unroll
                for (int kk = 0; kk < 4; kk++) acc[rr][kk] = fmaf(fv, w1v[kk], acc[rr][kk]);
            }
        }
        #pragma unroll
        for (int rr = 0; rr < 4; rr++)
            #pragma unroll
            for (int kk = 0; kk < 4; kk++)
                h2S[(4 * w + rr) * 132 + lane + 32 * kk] = sp(acc[rr][kk]);
    }
    __syncthreads();

    // ---- stage 2, layer 2: 512 threads = (row i, out-col p) ----
    if (tid < ITILE * FPRIME) {
        int i = tid >> 4, p = tid & 15;
        float o = b2S[p];
        #pragma unroll 8
        for (int hh = 0; hh < HDIM; hh++)
            o = fmaf(h2S[i * 132 + hh], w2S[hh * FPRIME + p], o);
        out[((size_t)(b * NPTS + i0 + i)) * FPRIME + p] = sp(o);
    }
}

// ---------------------------------------------------------------------------
extern "C" void kernel_launch(void* const* d_in, const int* in_sizes, int n_in,
                              void* d_out, int out_size) {
    const float* r     = (const float*)d_in[0];
    const float* f     = (const float*)d_in[1];
    const float* mp_w1 = (const float*)d_in[2];
    const float* mp_b1 = (const float*)d_in[3];
    const float* mp_w2 = (const float*)d_in[4];
    const float* mp_b2 = (const float*)d_in[5];
    const float* pc_w1 = (const float*)d_in[6];
    const float* pc_b1 = (const float*)d_in[7];
    const float* pc_w2 = (const float*)d_in[8];
    const float* pc_b2 = (const float*)d_in[9];
    float* out = (float*)d_out;

    build_lut_kernel<<<TLUT / 8, 128>>>(mp_w1, mp_b1, mp_w2, mp_b2);

    static int configured = 0;
    if (!configured) {
        cudaFuncSetAttribute(property_predictor_main,
                             cudaFuncAttributeMaxDynamicSharedMemorySize, 118784);
        configured = 1;
    }
    dim3 grid(NPTS / ITILE, BATCH);
    property_predictor_main<<<grid, MAIN_THREADS, 118784>>>(
        r, f, pc_w1, pc_b1, pc_w2, pc_b2, out);
}

// round 4
// speedup vs baseline: 3.3144x; 1.0985x over previous
#include <cuda_runtime.h>
#include <cuda_fp16.h>
#include <math.h>

#define BATCH   16
#define NPTS    256
#define FDIM    64
#define FPRIME  16
#define HDIM    128
#define TLUT    512
#define DMAX    1.7321f
#define ITILE   32
#define MAIN_THREADS 1024

// nearest-neighbor LUT: entry [t*32+p] = half2(v_{2p}(t*h), v_{2p+1}(t*h))
__device__ unsigned int g_lutH[TLUT * 32];

__device__ __forceinline__ float sp(float x) {
    return fmaxf(x, 0.0f) + log1pf(expf(-fabsf(x)));
}

// ---------------------------------------------------------------------------
// LUT build: 128 blocks x 4 knots. w2 staged in smem (L2-hit after wave 1).
// ---------------------------------------------------------------------------
__global__ __launch_bounds__(128)
void build_lut_kernel(const float* __restrict__ mp_w1,
                      const float* __restrict__ mp_b1,
                      const float* __restrict__ mp_w2,
                      const float* __restrict__ mp_b2) {
    __shared__ float w2s[HDIM * FDIM];     // 32 KB
    __shared__ float hid[4][HDIM];
    __shared__ float v[4][FDIM];

    const int blk = blockIdx.x;            // 0..127
    const int tid = threadIdx.x;           // 128
    const float h = DMAX / (float)TLUT;

    #pragma unroll 16
    for (int k = tid; k < HDIM * FDIM; k += 128) w2s[k] = mp_w2[k];
    {
        float w1 = mp_w1[tid], b1 = mp_b1[tid];
        #pragma unroll
        for (int e = 0; e < 4; e++) {
            float d = (float)(blk * 4 + e) * h;
            hid[e][tid] = sp(fmaf(d, w1, b1));
        }
    }
    __syncthreads();

    // 4 knots x 64 f = 256 dots over 128 threads -> 2 per thread
    {
        int e = tid >> 6;                  // 0..1 -> handles e and e+2
        int ff = tid & 63;
        float a0 = mp_b2[ff], a1 = a0;
        #pragma unroll 8
        for (int k = 0; k < HDIM; k++) {
            float w = w2s[k * FDIM + ff];
            a0 = fmaf(hid[e][k],     w, a0);
            a1 = fmaf(hid[e + 2][k], w, a1);
        }
        v[e][ff]     = sp(a0);
        v[e + 2][ff] = sp(a1);
    }
    __syncthreads();

    if (tid < 4 * 32) {
        int e = tid >> 5, p = tid & 31;
        __half2 vh = __floats2half2_rn(v[e][2 * p], v[e][2 * p + 1]);
        g_lutH[(blk * 4 + e) * 32 + p] = *reinterpret_cast<unsigned int*>(&vh);
    }
}

// ---------------------------------------------------------------------------
// Main fused kernel. CTA = (batch b, 32-row i-tile). 1024 threads, 1 CTA/SM.
// SMEM map (stage 1), 135168 B:
//   [0,      65536)  lutS  fp16 LUT (TLUT*32 half2)
//   [65536,  98304)  fbS   f tile as half2 (256 j * 32 lanes)
//   [98304, 131072)  tS    per-pair u32 LUT byte-offset, layout [j][i]
//   [131072,135168)  rS    positions float4 (256)
// Overlays:
//   part  @0       (32 i * 16 jg * 32 lane * half2 = 65536)   over lutS
//   fbar  @65536   (32*64 f32 = 8192)                          over fbS head
//   w1    @73728   (64*128 f32 = 32768)                        over fbS/tS
//   w2    @106496  (128*16 f32 = 8192)                         over tS
//   b1    @114688, b2 @115200                                  over tS
//   h2    @0       (32*132 f32, padded)                        over part
// ---------------------------------------------------------------------------
__global__ __launch_bounds__(MAIN_THREADS, 1)
void property_predictor_main(const float* __restrict__ r,
                             const float* __restrict__ f,
                             const float* __restrict__ pc_w1,
                             const float* __restrict__ pc_b1,
                             const float* __restrict__ pc_w2,
                             const float* __restrict__ pc_b2,
                             float* __restrict__ out) {
    extern __shared__ char smem[];
    unsigned int* lutS  = (unsigned int*)(smem);
    unsigned int* fbS   = (unsigned int*)(smem + 65536);
    unsigned int* tS    = (unsigned int*)(smem + 98304);
    float4*       rS    = (float4*)(smem + 131072);
    unsigned int* partS = (unsigned int*)(smem);
    float* fbarS = (float*)(smem + 65536);
    float* w1S   = (float*)(smem + 73728);
    float* w2S   = (float*)(smem + 106496);
    float* b1S   = (float*)(smem + 114688);
    float* b2S   = (float*)(smem + 115200);
    float* h2S   = (float*)(smem);

    const int b    = blockIdx.y;
    const int i0   = blockIdx.x * ITILE;
    const int tid  = threadIdx.x;
    const int w    = tid >> 5;
    const int lane = tid & 31;

    // ---- tile loads ----
    #pragma unroll 4
    for (int k = tid; k < TLUT * 32; k += MAIN_THREADS) lutS[k] = g_lutH[k];
    const float2* fbG = (const float2*)(f + (size_t)b * NPTS * FDIM);
    #pragma unroll 8
    for (int k = tid; k < NPTS * 32; k += MAIN_THREADS) {
        float2 v = fbG[k];
        __half2 hv = __floats2half2_rn(v.x, v.y);
        fbS[k] = *reinterpret_cast<unsigned int*>(&hv);
    }
    const float* rG = r + (size_t)b * NPTS * 3;
    if (tid < NPTS)
        rS[tid] = make_float4(rG[3 * tid], rG[3 * tid + 1], rG[3 * tid + 2], 0.0f);
    __syncthreads();

    // ---- stage A: per-pair nearest-knot byte offset, tS[j*32 + i] ----
    const float scale = (float)TLUT / DMAX;
    #pragma unroll
    for (int k = 0; k < (ITILE * NPTS) / MAIN_THREADS; k++) {
        int idx = tid + k * MAIN_THREADS;
        int jj = idx >> 5, ii = idx & 31;
        float4 ri = rS[i0 + ii];
        float4 rj = rS[jj];
        float dx = ri.x - rj.x, dy = ri.y - rj.y, dz = ri.z - rj.z;
        float d  = sqrtf(fmaf(dx, dx, fmaf(dy, dy, dz * dz)));
        int   it = (int)(fmaf(d, scale, 0.5f));
        it = min(it, TLUT - 1);
        tS[idx] = (unsigned int)(it << 7);      // byte offset: it * 32 entries * 4B
    }
    __syncthreads();

    // ---- stage 1: warp tile = 16 i x 16 j; lane owns f-pair (2*lane,2*lane+1)
    const int ig = w >> 4;                      // i half: rows ig*16 .. +15
    const int jg = w & 15;                      // j block: jg*16 .. +15
    const char* lutLane = smem + (size_t)lane * 4;

    __half2 acc[16];
    const __half2 hzero = __floats2half2_rn(0.0f, 0.0f);
    #pragma unroll
    for (int ii = 0; ii < 16; ii++) acc[ii] = hzero;

    #pragma unroll
    for (int jj = 0; jj < 16; jj++) {
        const int j = jg * 16 + jj;
        unsigned int fbits = fbS[(j << 5) + lane];
        __half2 fb2 = *reinterpret_cast<__half2*>(&fbits);
        const uint4* tp = (const uint4*)(tS + (j << 5) + ig * 16);
        uint4 o0 = tp[0], o1 = tp[1], o2 = tp[2], o3 = tp[3];  // broadcasts
        unsigned int off[16] = {o0.x, o0.y, o0.z, o0.w, o1.x, o1.y, o1.z, o1.w,
                                o2.x, o2.y, o2.z, o2.w, o3.x, o3.y, o3.z, o3.w};
        #pragma unroll
        for (int ii = 0; ii < 16; ii++) {
            __half2 L = *(const __half2*)(lutLane + off[ii]);
            acc[ii] = __hfma2(L, fb2, acc[ii]);
        }
    }
    __syncthreads();   // all lutS/fbS/tS reads complete

    // ---- write partials over lutS; stage pointwise weights over fbS/tS/rS ----
    #pragma unroll
    for (int ii = 0; ii < 16; ii++) {
        int i = ig * 16 + ii;
        partS[((i << 4) + jg) * 32 + lane] = *reinterpret_cast<unsigned int*>(&acc[ii]);
    }
    #pragma unroll 8
    for (int k = tid; k < FDIM * HDIM;   k += MAIN_THREADS) w1S[k] = pc_w1[k];
    #pragma unroll 2
    for (int k = tid; k < HDIM * FPRIME; k += MAIN_THREADS) w2S[k] = pc_w2[k];
    if (tid < HDIM)   b1S[tid] = pc_b1[tid];
    if (tid < FPRIME) b2S[tid] = pc_b2[tid];
    __syncthreads();

    // ---- reduction: thread (i, lane) sums 16 jg partials in fp32 ----
    {
        int i = w;                              // 32 warps = 32 rows
        float sx = 0.0f, sy = 0.0f;
        #pragma unroll
        for (int g = 0; g < 16; g++) {
            unsigned int pbits = partS[((i << 4) + g) * 32 + lane];
            float2 pv = __half22float2(*reinterpret_cast<__half2*>(&pbits));
            sx += pv.x; sy += pv.y;
        }
        fbarS[i * FDIM + 2 * lane]     = sp(sx);
        fbarS[i * FDIM + 2 * lane + 1] = sp(sy);
    }
    __syncthreads();

    // ---- stage 2, layer 1: warps 0..7, 4 rows each; lane owns 4 h-cols ----
    if (w < 8) {
        float acc2[4][4];
        #pragma unroll
        for (int kk = 0; kk < 4; kk++) {
            float bv = b1S[lane + 32 * kk];
            #pragma unroll
            for (int rr = 0; rr < 4; rr++) acc2[rr][kk] = bv;
        }
        #pragma unroll 4
        for (int ff = 0; ff < FDIM; ff++) {
            float w1v[4];
            #pragma unroll
            for (int kk = 0; kk < 4; kk++) w1v[kk] = w1S[ff * HDIM + lane + 32 * kk];
            #pragma unroll
            for (int rr = 0; rr < 4; rr++) {
                float fv = fbarS[(4 * w + rr) * FDIM + ff];
                #pragma unroll
                for (int kk = 0; kk < 4; kk++) acc2[rr][kk] = fmaf(fv, w1v[kk], acc2[rr][kk]);
            }
        }
        #pragma unroll
        for (int rr = 0; rr < 4; rr++)
            #pragma unroll
            for (int kk = 0; kk < 4; kk++)
                h2S[(4 * w + rr) * 132 + lane + 32 * kk] = sp(acc2[rr][kk]);
    }
    __syncthreads();

    // ---- stage 2, layer 2: 512 threads = (row i, out-col p) ----
    if (tid < ITILE * FPRIME) {
        int i = tid >> 4, p = tid & 15;
        float o = b2S[p];
        #pragma unroll 8
        for (int hh = 0; hh < HDIM; hh++)
            o = fmaf(h2S[i * 132 + hh], w2S[hh * FPRIME + p], o);
        out[((size_t)(b * NPTS + i0 + i)) * FPRIME + p] = sp(o);
    }
}

// ---------------------------------------------------------------------------
extern "C" void kernel_launch(void* const* d_in, const int* in_sizes, int n_in,
                              void* d_out, int out_size) {
    const float* r     = (const float*)d_in[0];
    const float* f     = (const float*)d_in[1];
    const float* mp_w1 = (const float*)d_in[2];
    const float* mp_b1 = (const float*)d_in[3];
    const float* mp_w2 = (const float*)d_in[4];
    const float* mp_b2 = (const float*)d_in[5];
    const float* pc_w1 = (const float*)d_in[6];
    const float* pc_b1 = (const float*)d_in[7];
    const float* pc_w2 = (const float*)d_in[8];
    const float* pc_b2 = (const float*)d_in[9];
    float* out = (float*)d_out;

    build_lut_kernel<<<TLUT / 4, 128>>>(mp_w1, mp_b1, mp_w2, mp_b2);

    static int configured = 0;
    if (!configured) {
        cudaFuncSetAttribute(property_predictor_main,
                             cudaFuncAttributeMaxDynamicSharedMemorySize, 135168);
        configured = 1;
    }
    dim3 grid(NPTS / ITILE, BATCH);
    property_predictor_main<<<grid, MAIN_THREADS, 135168>>>(
        r, f, pc_w1, pc_b1, pc_w2, pc_b2, out);
}

// round 5
// speedup vs baseline: 3.3186x; 1.0013x over previous
#include <cuda_runtime.h>
#include <cuda_fp16.h>
#include <math.h>

#define BATCH   16
#define NPTS    256
#define FDIM    64
#define FPRIME  16
#define HDIM    128
#define TLUT    512
#define DMAX    1.7321f
#define ITILE   32
#define MAIN_THREADS 1024

// nearest-neighbor LUT: entry [t*32+p] = half2(v_{2p}(t*h), v_{2p+1}(t*h))
__device__ unsigned int g_lutH[TLUT * 32];

__device__ __forceinline__ float sp(float x) {
    return fmaxf(x, 0.0f) + log1pf(expf(-fabsf(x)));
}

// ---------------------------------------------------------------------------
// LUT build: 128 blocks x 4 knots. w2 staged in smem (L2-hit after wave 1).
// ---------------------------------------------------------------------------
__global__ __launch_bounds__(128)
void build_lut_kernel(const float* __restrict__ mp_w1,
                      const float* __restrict__ mp_b1,
                      const float* __restrict__ mp_w2,
                      const float* __restrict__ mp_b2) {
    __shared__ float w2s[HDIM * FDIM];     // 32 KB
    __shared__ float hid[4][HDIM];
    __shared__ float v[4][FDIM];

    const int blk = blockIdx.x;            // 0..127
    const int tid = threadIdx.x;           // 128
    const float h = DMAX / (float)TLUT;

    #pragma unroll 16
    for (int k = tid; k < HDIM * FDIM; k += 128) w2s[k] = mp_w2[k];
    {
        float w1 = mp_w1[tid], b1 = mp_b1[tid];
        #pragma unroll
        for (int e = 0; e < 4; e++) {
            float d = (float)(blk * 4 + e) * h;
            hid[e][tid] = sp(fmaf(d, w1, b1));
        }
    }
    __syncthreads();

    // 4 knots x 64 f = 256 dots over 128 threads -> 2 per thread
    {
        int e = tid >> 6;                  // 0..1 -> handles e and e+2
        int ff = tid & 63;
        float a0 = mp_b2[ff], a1 = a0;
        #pragma unroll 8
        for (int k = 0; k < HDIM; k++) {
            float w = w2s[k * FDIM + ff];
            a0 = fmaf(hid[e][k],     w, a0);
            a1 = fmaf(hid[e + 2][k], w, a1);
        }
        v[e][ff]     = sp(a0);
        v[e + 2][ff] = sp(a1);
    }
    __syncthreads();

    if (tid < 4 * 32) {
        int e = tid >> 5, p = tid & 31;
        __half2 vh = __floats2half2_rn(v[e][2 * p], v[e][2 * p + 1]);
        g_lutH[(blk * 4 + e) * 32 + p] = *reinterpret_cast<unsigned int*>(&vh);
    }
}

// ---------------------------------------------------------------------------
// Main fused kernel. CTA = (batch b, 32-row i-tile). 1024 threads, 1 CTA/SM.
// SMEM map (stage 1), 135168 B:
//   [0,      65536)  lutS  fp16 LUT (TLUT*32 half2)
//   [65536,  98304)  fbS   f tile as half2 (256 j * 32 lanes)
//   [98304, 131072)  tS    per-pair u32 LUT byte-offset, layout [j][i]
//   [131072,135168)  rS    positions float4 (256)
// Overlays:
//   part  @0       (32 i * 16 jg * 32 lane * half2 = 65536)   over lutS
//   fbar  @65536   (32*64 f32 = 8192)                          over fbS head
//   w1    @73728   (64*128 f32 = 32768)                        over fbS/tS
//   w2    @106496  (128*16 f32 = 8192)                         over tS
//   b1    @114688, b2 @115200                                  over tS
//   h2    @0       (32*132 f32, padded)                        over part
// ---------------------------------------------------------------------------
__global__ __launch_bounds__(MAIN_THREADS, 1)
void property_predictor_main(const float* __restrict__ r,
                             const float* __restrict__ f,
                             const float* __restrict__ pc_w1,
                             const float* __restrict__ pc_b1,
                             const float* __restrict__ pc_w2,
                             const float* __restrict__ pc_b2,
                             float* __restrict__ out) {
    extern __shared__ char smem[];
    unsigned int* lutS  = (unsigned int*)(smem);
    unsigned int* fbS   = (unsigned int*)(smem + 65536);
    unsigned int* tS    = (unsigned int*)(smem + 98304);
    float4*       rS    = (float4*)(smem + 131072);
    unsigned int* partS = (unsigned int*)(smem);
    float* fbarS = (float*)(smem + 65536);
    float* w1S   = (float*)(smem + 73728);
    float* w2S   = (float*)(smem + 106496);
    float* b1S   = (float*)(smem + 114688);
    float* b2S   = (float*)(smem + 115200);
    float* h2S   = (float*)(smem);

    const int b    = blockIdx.y;
    const int i0   = blockIdx.x * ITILE;
    const int tid  = threadIdx.x;
    const int w    = tid >> 5;
    const int lane = tid & 31;

    // ---- tile loads ----
    #pragma unroll 4
    for (int k = tid; k < TLUT * 32; k += MAIN_THREADS) lutS[k] = g_lutH[k];
    const float2* fbG = (const float2*)(f + (size_t)b * NPTS * FDIM);
    #pragma unroll 8
    for (int k = tid; k < NPTS * 32; k += MAIN_THREADS) {
        float2 v = fbG[k];
        __half2 hv = __floats2half2_rn(v.x, v.y);
        fbS[k] = *reinterpret_cast<unsigned int*>(&hv);
    }
    const float* rG = r + (size_t)b * NPTS * 3;
    if (tid < NPTS)
        rS[tid] = make_float4(rG[3 * tid], rG[3 * tid + 1], rG[3 * tid + 2], 0.0f);
    __syncthreads();

    // ---- stage A: per-pair nearest-knot byte offset, tS[j*32 + i] ----
    const float scale = (float)TLUT / DMAX;
    #pragma unroll
    for (int k = 0; k < (ITILE * NPTS) / MAIN_THREADS; k++) {
        int idx = tid + k * MAIN_THREADS;
        int jj = idx >> 5, ii = idx & 31;
        float4 ri = rS[i0 + ii];
        float4 rj = rS[jj];
        float dx = ri.x - rj.x, dy = ri.y - rj.y, dz = ri.z - rj.z;
        float d  = sqrtf(fmaf(dx, dx, fmaf(dy, dy, dz * dz)));
        int   it = (int)(fmaf(d, scale, 0.5f));
        it = min(it, TLUT - 1);
        tS[idx] = (unsigned int)(it << 7);      // byte offset: it * 32 entries * 4B
    }
    __syncthreads();

    // ---- stage 1: warp tile = 16 i x 16 j; lane owns f-pair (2*lane,2*lane+1)
    const int ig = w >> 4;                      // i half: rows ig*16 .. +15
    const int jg = w & 15;                      // j block: jg*16 .. +15
    const char* lutLane = smem + (size_t)lane * 4;

    __half2 acc[16];
    const __half2 hzero = __floats2half2_rn(0.0f, 0.0f);
    #pragma unroll
    for (int ii = 0; ii < 16; ii++) acc[ii] = hzero;

    #pragma unroll
    for (int jj = 0; jj < 16; jj++) {
        const int j = jg * 16 + jj;
        unsigned int fbits = fbS[(j << 5) + lane];
        __half2 fb2 = *reinterpret_cast<__half2*>(&fbits);
        const uint4* tp = (const uint4*)(tS + (j << 5) + ig * 16);
        uint4 o0 = tp[0], o1 = tp[1], o2 = tp[2], o3 = tp[3];  // broadcasts
        unsigned int off[16] = {o0.x, o0.y, o0.z, o0.w, o1.x, o1.y, o1.z, o1.w,
                                o2.x, o2.y, o2.z, o2.w, o3.x, o3.y, o3.z, o3.w};
        #pragma unroll
        for (int ii = 0; ii < 16; ii++) {
            __half2 L = *(const __half2*)(lutLane + off[ii]);
            acc[ii] = __hfma2(L, fb2, acc[ii]);
        }
    }
    __syncthreads();   // all lutS/fbS/tS reads complete

    // ---- write partials over lutS; stage pointwise weights over fbS/tS/rS ----
    #pragma unroll
    for (int ii = 0; ii < 16; ii++) {
        int i = ig * 16 + ii;
        partS[((i << 4) + jg) * 32 + lane] = *reinterpret_cast<unsigned int*>(&acc[ii]);
    }
    #pragma unroll 8
    for (int k = tid; k < FDIM * HDIM;   k += MAIN_THREADS) w1S[k] = pc_w1[k];
    #pragma unroll 2
    for (int k = tid; k < HDIM * FPRIME; k += MAIN_THREADS) w2S[k] = pc_w2[k];
    if (tid < HDIM)   b1S[tid] = pc_b1[tid];
    if (tid < FPRIME) b2S[tid] = pc_b2[tid];
    __syncthreads();

    // ---- reduction: thread (i, lane) sums 16 jg partials in fp32 ----
    {
        int i = w;                              // 32 warps = 32 rows
        float sx = 0.0f, sy = 0.0f;
        #pragma unroll
        for (int g = 0; g < 16; g++) {
            unsigned int pbits = partS[((i << 4) + g) * 32 + lane];
            float2 pv = __half22float2(*reinterpret_cast<__half2*>(&pbits));
            sx += pv.x; sy += pv.y;
        }
        fbarS[i * FDIM + 2 * lane]     = sp(sx);
        fbarS[i * FDIM + 2 * lane + 1] = sp(sy);
    }
    __syncthreads();

    // ---- stage 2, layer 1: warps 0..7, 4 rows each; lane owns 4 h-cols ----
    if (w < 8) {
        float acc2[4][4];
        #pragma unroll
        for (int kk = 0; kk < 4; kk++) {
            float bv = b1S[lane + 32 * kk];
            #pragma unroll
            for (int rr = 0; rr < 4; rr++) acc2[rr][kk] = bv;
        }
        #pragma unroll 4
        for (int ff = 0; ff < FDIM; ff++) {
            float w1v[4];
            #pragma unroll
            for (int kk = 0; kk < 4; kk++) w1v[kk] = w1S[ff * HDIM + lane + 32 * kk];
            #pragma unroll
            for (int rr = 0; rr < 4; rr++) {
                float fv = fbarS[(4 * w + rr) * FDIM + ff];
                #pragma unroll
                for (int kk = 0; kk < 4; kk++) acc2[rr][kk] = fmaf(fv, w1v[kk], acc2[rr][kk]);
            }
        }
        #pragma unroll
        for (int rr = 0; rr < 4; rr++)
            #pragma unroll
            for (int kk = 0; kk < 4; kk++)
                h2S[(4 * w + rr) * 132 + lane + 32 * kk] = sp(acc2[rr][kk]);
    }
    __syncthreads();

    // ---- stage 2, layer 2: 512 threads = (row i, out-col p) ----
    if (tid < ITILE * FPRIME) {
        int i = tid >> 4, p = tid & 15;
        float o = b2S[p];
        #pragma unroll 8
        for (int hh = 0; hh < HDIM; hh++)
            o = fmaf(h2S[i * 132 + hh], w2S[hh * FPRIME + p], o);
        out[((size_t)(b * NPTS + i0 + i)) * FPRIME + p] = sp(o);
    }
}

// ---------------------------------------------------------------------------
extern "C" void kernel_launch(void* const* d_in, const int* in_sizes, int n_in,
                              void* d_out, int out_size) {
    const float* r     = (const float*)d_in[0];
    const float* f     = (const float*)d_in[1];
    const float* mp_w1 = (const float*)d_in[2];
    const float* mp_b1 = (const float*)d_in[3];
    const float* mp_w2 = (const float*)d_in[4];
    const float* mp_b2 = (const float*)d_in[5];
    const float* pc_w1 = (const float*)d_in[6];
    const float* pc_b1 = (const float*)d_in[7];
    const float* pc_w2 = (const float*)d_in[8];
    const float* pc_b2 = (const float*)d_in[9];
    float* out = (float*)d_out;

    build_lut_kernel<<<TLUT / 4, 128>>>(mp_w1, mp_b1, mp_w2, mp_b2);

    static int configured = 0;
    if (!configured) {
        cudaFuncSetAttribute(property_predictor_main,
                             cudaFuncAttributeMaxDynamicSharedMemorySize, 135168);
        configured = 1;
    }
    dim3 grid(NPTS / ITILE, BATCH);
    property_predictor_main<<<grid, MAIN_THREADS, 135168>>>(
        r, f, pc_w1, pc_b1, pc_w2, pc_b2, out);
}

// round 6
// speedup vs baseline: 3.3312x; 1.0038x over previous
#include <cuda_runtime.h>
#include <cuda_fp16.h>
#include <math.h>

#define BATCH   16
#define NPTS    256
#define FDIM    64
#define FPRIME  16
#define HDIM    128
#define TLUT    512
#define DMAX    1.7321f
#define ITILE   16
#define MAIN_THREADS 512

// nearest-neighbor LUT: entry [t*32+p] = half2(v_{2p}(t*h), v_{2p+1}(t*h))
__device__ unsigned int g_lutH[TLUT * 32];

__device__ __forceinline__ float sp(float x) {
    return fmaxf(x, 0.0f) + log1pf(expf(-fabsf(x)));
}

// ---------------------------------------------------------------------------
// LUT build: 64 blocks x 8 knots x 256 threads. w2 staged via float4.
// ---------------------------------------------------------------------------
__global__ __launch_bounds__(256)
void build_lut_kernel(const float* __restrict__ mp_w1,
                      const float* __restrict__ mp_b1,
                      const float* __restrict__ mp_w2,
                      const float* __restrict__ mp_b2) {
    __shared__ float w2s[HDIM * FDIM];     // 32 KB
    __shared__ float hid[8][HDIM];
    __shared__ float v[8][FDIM];

    const int blk = blockIdx.x;            // 0..63
    const int tid = threadIdx.x;           // 256
    const float hstep = DMAX / (float)TLUT;

    const float4* w2v = (const float4*)mp_w2;
    float4* w2sv = (float4*)w2s;
    #pragma unroll
    for (int k = tid; k < HDIM * FDIM / 4; k += 256) w2sv[k] = w2v[k];
    #pragma unroll
    for (int k = tid; k < 8 * HDIM; k += 256) {
        int e = k >> 7, hh = k & 127;
        float d = (float)(blk * 8 + e) * hstep;
        hid[e][hh] = sp(fmaf(d, mp_w1[hh], mp_b1[hh]));
    }
    __syncthreads();

    {   // 8 knots x 64 f = 512 dots over 256 threads -> 2 each (e, e+4)
        int e = tid >> 6;                  // 0..3
        int ff = tid & 63;
        float a0 = mp_b2[ff], a1 = a0;
        #pragma unroll 8
        for (int k = 0; k < HDIM; k++) {
            float w = w2s[k * FDIM + ff];
            a0 = fmaf(hid[e][k],     w, a0);
            a1 = fmaf(hid[e + 4][k], w, a1);
        }
        v[e][ff]     = sp(a0);
        v[e + 4][ff] = sp(a1);
    }
    __syncthreads();

    {   // pack 8*32 entries, one per thread
        int e = tid >> 5, p = tid & 31;
        __half2 vh = __floats2half2_rn(v[e][2 * p], v[e][2 * p + 1]);
        g_lutH[(blk * 8 + e) * 32 + p] = *reinterpret_cast<unsigned int*>(&vh);
    }
}

// ---------------------------------------------------------------------------
// Main fused kernel. CTA = (batch b, 16-row i-tile). 512 threads, 2 CTAs/SM.
// SMEM map (110592 B):
//   [0,      65536)  lutS  fp16 LUT (TLUT*32 half2)
//   [65536,  98304)  fbS   f tile half2 (256 j * 32 lanes)
//   [98304, 106496)  tS    u16 pre-shifted LUT byte-offset, layout [j][i]
//   [106496,110592)  rS    positions float4 (256)
// Overlays:
//   partS @0      (16 i * 16 g * 32 lane u32 = 32768)        over lutS
//   fbarT @32768  (64 f * stride 18 f32 = 4608)              over lutS
//   w1S   @65536  (64*128 f32)                               over fbS
//   w2T   @98304  (16 p * stride 132 f32 = 8448)             over tS+
//   b1S   @106752, b2S @107264                               over rS
//   h2S   @0      (16 * 132 f32, after reduction sync)       over partS
// ---------------------------------------------------------------------------
__global__ __launch_bounds__(MAIN_THREADS, 2)
void property_predictor_main(const float* __restrict__ r,
                             const float* __restrict__ f,
                             const float* __restrict__ pc_w1,
                             const float* __restrict__ pc_b1,
                             const float* __restrict__ pc_w2,
                             const float* __restrict__ pc_b2,
                             float* __restrict__ out) {
    extern __shared__ char smem[];
    unsigned int*   lutS = (unsigned int*)(smem);
    unsigned int*   fbS  = (unsigned int*)(smem + 65536);
    unsigned short* tS   = (unsigned short*)(smem + 98304);
    float4*         rS   = (float4*)(smem + 106496);
    unsigned int*   partS = (unsigned int*)(smem);
    float* fbarT = (float*)(smem + 32768);
    float* w1S   = (float*)(smem + 65536);
    float* w2T   = (float*)(smem + 98304);
    float* b1S   = (float*)(smem + 106752);
    float* b2S   = (float*)(smem + 107264);
    float* h2S   = (float*)(smem);

    const int b    = blockIdx.y;
    const int i0   = blockIdx.x * ITILE;
    const int tid  = threadIdx.x;
    const int w    = tid >> 5;
    const int lane = tid & 31;

    // ---- tile loads (vectorized) ----
    const uint4* lutG = (const uint4*)g_lutH;
    uint4* lutSv = (uint4*)lutS;
    #pragma unroll
    for (int k = tid; k < TLUT * 8; k += MAIN_THREADS) lutSv[k] = lutG[k];
    const float4* fbG = (const float4*)(f + (size_t)b * NPTS * FDIM);
    #pragma unroll
    for (int k = tid; k < NPTS * 16; k += MAIN_THREADS) {
        float4 v = fbG[k];
        __half2 h0 = __floats2half2_rn(v.x, v.y);
        __half2 h1 = __floats2half2_rn(v.z, v.w);
        fbS[2 * k]     = *reinterpret_cast<unsigned int*>(&h0);
        fbS[2 * k + 1] = *reinterpret_cast<unsigned int*>(&h1);
    }
    const float* rG = r + (size_t)b * NPTS * 3;
    if (tid < NPTS)
        rS[tid] = make_float4(rG[3 * tid], rG[3 * tid + 1], rG[3 * tid + 2], 0.0f);
    __syncthreads();

    // ---- stage A: per-pair nearest-knot byte offset (u16), tS[j*16 + i] ----
    const float scale = (float)TLUT / DMAX;
    #pragma unroll
    for (int k = 0; k < (ITILE * NPTS) / MAIN_THREADS; k++) {
        int idx = tid + k * MAIN_THREADS;
        int jj = idx >> 4, ii = idx & 15;
        float4 ri = rS[i0 + ii];
        float4 rj = rS[jj];
        float dx = ri.x - rj.x, dy = ri.y - rj.y, dz = ri.z - rj.z;
        float d  = sqrtf(fmaf(dx, dx, fmaf(dy, dy, dz * dz)));
        int   it = (int)(fmaf(d, scale, 0.5f));
        it = min(it, TLUT - 1);
        tS[idx] = (unsigned short)(it << 7);   // byte offset = it * 32 entries * 4B
    }
    __syncthreads();

    // ---- stage 1: warp w owns j in [16w,16w+16); all 16 i; lane = f-pair ----
    const char*  lutLane = smem + (size_t)lane * 4;
    const uint4* tRow    = (const uint4*)(smem + 98304 + (size_t)w * 512);

    __half2 acc[16];
    const __half2 hzero = __float2half2_rn(0.0f);
    #pragma unroll
    for (int ii = 0; ii < 16; ii++) acc[ii] = hzero;

    #pragma unroll
    for (int jj = 0; jj < 16; jj++) {
        const int j = (w << 4) + jj;
        unsigned int fbits = fbS[(j << 5) + lane];
        __half2 fb2 = *reinterpret_cast<__half2*>(&fbits);
        uint4 q0 = tRow[2 * jj], q1 = tRow[2 * jj + 1];      // broadcast, 16 u16 offs
        unsigned int off[16] = {
            q0.x & 0xFFFFu, q0.x >> 16, q0.y & 0xFFFFu, q0.y >> 16,
            q0.z & 0xFFFFu, q0.z >> 16, q0.w & 0xFFFFu, q0.w >> 16,
            q1.x & 0xFFFFu, q1.x >> 16, q1.y & 0xFFFFu, q1.y >> 16,
            q1.z & 0xFFFFu, q1.z >> 16, q1.w & 0xFFFFu, q1.w >> 16};
        #pragma unroll
        for (int ii = 0; ii < 16; ii++) {
            __half2 L = *(const __half2*)(lutLane + off[ii]);
            acc[ii] = __hfma2(L, fb2, acc[ii]);
        }
    }
    __syncthreads();   // all lutS/fbS/tS reads complete

    // ---- write partials over lutS; stage pointwise weights ----
    #pragma unroll
    for (int ii = 0; ii < 16; ii++)
        partS[((ii << 4) + w) * 32 + lane] = *reinterpret_cast<unsigned int*>(&acc[ii]);
    #pragma unroll
    for (int k = tid; k < FDIM * HDIM; k += MAIN_THREADS) w1S[k] = pc_w1[k];
    #pragma unroll
    for (int k = tid; k < HDIM * FPRIME; k += MAIN_THREADS) {
        int hh = k >> 4, p = k & 15;
        w2T[p * 132 + hh] = pc_w2[k];          // transposed for layer-2 vector loads
    }
    if (tid < HDIM)   b1S[tid] = pc_b1[tid];
    if (tid < FPRIME) b2S[tid] = pc_b2[tid];
    __syncthreads();

    // ---- reduction: warp w = row i; fp32 sum of 16 group partials ----
    {
        float sx = 0.0f, sy = 0.0f;
        #pragma unroll
        for (int g = 0; g < 16; g++) {
            unsigned int pbits = partS[((w << 4) + g) * 32 + lane];
            float2 pv = __half22float2(*reinterpret_cast<__half2*>(&pbits));
            sx += pv.x; sy += pv.y;
        }
        fbarT[(2 * lane) * 18 + w]     = sp(sx);   // transposed [f][i], stride 18
        fbarT[(2 * lane + 1) * 18 + w] = sp(sy);
    }
    __syncthreads();

    // ---- stage 2 layer 1: warps 0..7, rows (2w,2w+1); lane owns 4 h-cols ----
    if (w < 8) {
        float a0[4], a1[4];
        #pragma unroll
        for (int kk = 0; kk < 4; kk++) { a0[kk] = b1S[lane + 32 * kk]; a1[kk] = a0[kk]; }
        #pragma unroll 8
        for (int ff = 0; ff < FDIM; ff++) {
            float2 fv = *(const float2*)(fbarT + ff * 18 + 2 * w);   // broadcast
            #pragma unroll
            for (int kk = 0; kk < 4; kk++) {
                float wv = w1S[ff * HDIM + lane + 32 * kk];
                a0[kk] = fmaf(fv.x, wv, a0[kk]);
                a1[kk] = fmaf(fv.y, wv, a1[kk]);
            }
        }
        #pragma unroll
        for (int kk = 0; kk < 4; kk++) {
            h2S[(2 * w) * 132 + lane + 32 * kk]     = sp(a0[kk]);
            h2S[(2 * w + 1) * 132 + lane + 32 * kk] = sp(a1[kk]);
        }
    }
    __syncthreads();

    // ---- stage 2 layer 2: 256 threads = (row i, out-col p), float4 loads ----
    if (tid < ITILE * FPRIME) {
        int i = tid >> 4, p = tid & 15;
        float o = b2S[p];
        const float4* h2v = (const float4*)(h2S + i * 132);
        const float4* w2v = (const float4*)(w2T + p * 132);
        #pragma unroll 8
        for (int hh = 0; hh < HDIM / 4; hh++) {
            float4 hv = h2v[hh];
            float4 wv = w2v[hh];
            o = fmaf(hv.x, wv.x, o);
            o = fmaf(hv.y, wv.y, o);
            o = fmaf(hv.z, wv.z, o);
            o = fmaf(hv.w, wv.w, o);
        }
        out[((size_t)(b * NPTS + i0 + i)) * FPRIME + p] = sp(o);
    }
}

// ---------------------------------------------------------------------------
extern "C" void kernel_launch(void* const* d_in, const int* in_sizes, int n_in,
                              void* d_out, int out_size) {
    const float* r     = (const float*)d_in[0];
    const float* f     = (const float*)d_in[1];
    const float* mp_w1 = (const float*)d_in[2];
    const float* mp_b1 = (const float*)d_in[3];
    const float* mp_w2 = (const float*)d_in[4];
    const float* mp_b2 = (const float*)d_in[5];
    const float* pc_w1 = (const float*)d_in[6];
    const float* pc_b1 = (const float*)d_in[7];
    const float* pc_w2 = (const float*)d_in[8];
    const float* pc_b2 = (const float*)d_in[9];
    float* out = (float*)d_out;

    build_lut_kernel<<<TLUT / 8, 256>>>(mp_w1, mp_b1, mp_w2, mp_b2);

    cudaFuncSetAttribute(property_predictor_main,
                         cudaFuncAttributeMaxDynamicSharedMemorySize, 110592);
    dim3 grid(NPTS / ITILE, BATCH);
    property_predictor_main<<<grid, MAIN_THREADS, 110592>>>(
        r, f, pc_w1, pc_b1, pc_w2, pc_b2, out);
}